// round 1
// baseline (speedup 1.0000x reference)
#include <cuda_runtime.h>
#include <math.h>
#include <stdint.h>

#define T_STEPS 1024
#define BATCH   64
#define IN_DIM  512
#define H_DIM   1024

#define NCTA         128
#define SCAN_THREADS 128
#define COLS_PER_CTA 8          // 128 CTAs * 8 cols = 1024 = H_DIM
#define KCHUNK       128        // k-chunk staged in smem per double-buffer slot
#define NCHUNKS      (H_DIM / KCHUNK)

// Transposed hidden state, double-buffered: g_ht[p][col*BATCH + row]
__device__ float g_ht[2][H_DIM * BATCH];
// Monotonic grid barrier counter (u64: never wraps across graph replays)
__device__ unsigned long long g_bar = 0ULL;

// ---------------------------------------------------------------------------
// Kernel 0: transpose initial h (B,H) into g_ht[0] (H,B)
// ---------------------------------------------------------------------------
__global__ void transpose_h_kernel(const float* __restrict__ h)
{
    int idx = blockIdx.x * blockDim.x + threadIdx.x;   // 0 .. 65535
    int r = idx >> 10;          // batch row 0..63
    int c = idx & 1023;         // hidden col 0..1023
    g_ht[0][c * BATCH + r] = h[idx];
}

// ---------------------------------------------------------------------------
// Kernel 1: xproj = x @ Wx + b  written into out (which doubles as xproj buf)
// M = T*B = 65536, K = IN_DIM = 512, N = H_DIM = 1024
// Tiles: BM=64, BN=64, BK=16; 256 threads; 4x4 per-thread microtile.
// ---------------------------------------------------------------------------
__global__ void __launch_bounds__(256) xproj_kernel(
    const float* __restrict__ x,
    const float* __restrict__ W,     // full (IN+H, H); Wx = rows [0,512)
    const float* __restrict__ bias,
    float* __restrict__ out)
{
    __shared__ float As[16][64];     // [k][m]
    __shared__ float Bs[16][64];     // [k][n]

    const int tid  = threadIdx.x;
    const int row0 = blockIdx.y * 64;
    const int col0 = blockIdx.x * 64;

    const int ty = tid >> 4;               // 0..15 (row group)
    const int tx = tid & 15;               // 0..15 (col group)

    const int lmA = tid >> 2;              // 0..63
    const int lkA = (tid & 3) << 2;        // 0,4,8,12
    const int lkB = tid >> 4;              // 0..15
    const int lnB = (tid & 15) << 2;       // 0..60

    float acc[4][4];
#pragma unroll
    for (int i = 0; i < 4; ++i)
#pragma unroll
        for (int j = 0; j < 4; ++j) acc[i][j] = 0.0f;

    const float* xg = x + (size_t)(row0 + lmA) * IN_DIM + lkA;

    for (int k0 = 0; k0 < IN_DIM; k0 += 16) {
        float4 av = *(const float4*)(xg + k0);
        As[lkA + 0][lmA] = av.x;
        As[lkA + 1][lmA] = av.y;
        As[lkA + 2][lmA] = av.z;
        As[lkA + 3][lmA] = av.w;

        float4 bv = *(const float4*)(W + (size_t)(k0 + lkB) * H_DIM + col0 + lnB);
        *(float4*)&Bs[lkB][lnB] = bv;

        __syncthreads();
#pragma unroll
        for (int k = 0; k < 16; ++k) {
            float4 a = *(const float4*)&As[k][ty << 2];
            float4 b = *(const float4*)&Bs[k][tx << 2];
            acc[0][0] = fmaf(a.x, b.x, acc[0][0]);
            acc[0][1] = fmaf(a.x, b.y, acc[0][1]);
            acc[0][2] = fmaf(a.x, b.z, acc[0][2]);
            acc[0][3] = fmaf(a.x, b.w, acc[0][3]);
            acc[1][0] = fmaf(a.y, b.x, acc[1][0]);
            acc[1][1] = fmaf(a.y, b.y, acc[1][1]);
            acc[1][2] = fmaf(a.y, b.z, acc[1][2]);
            acc[1][3] = fmaf(a.y, b.w, acc[1][3]);
            acc[2][0] = fmaf(a.z, b.x, acc[2][0]);
            acc[2][1] = fmaf(a.z, b.y, acc[2][1]);
            acc[2][2] = fmaf(a.z, b.z, acc[2][2]);
            acc[2][3] = fmaf(a.z, b.w, acc[2][3]);
            acc[3][0] = fmaf(a.w, b.x, acc[3][0]);
            acc[3][1] = fmaf(a.w, b.y, acc[3][1]);
            acc[3][2] = fmaf(a.w, b.z, acc[3][2]);
            acc[3][3] = fmaf(a.w, b.w, acc[3][3]);
        }
        __syncthreads();
    }

    float4 bb = *(const float4*)(bias + col0 + (tx << 2));
#pragma unroll
    for (int i = 0; i < 4; ++i) {
        float4 o;
        o.x = acc[i][0] + bb.x;
        o.y = acc[i][1] + bb.y;
        o.z = acc[i][2] + bb.z;
        o.w = acc[i][3] + bb.w;
        *(float4*)(out + (size_t)(row0 + (ty << 2) + i) * H_DIM + col0 + (tx << 2)) = o;
    }
}

// ---------------------------------------------------------------------------
// Scan kernel helpers
// ---------------------------------------------------------------------------
__device__ __forceinline__ void cp_async16(float* sdst, const float* gsrc)
{
    unsigned sa = (unsigned)__cvta_generic_to_shared(sdst);
    asm volatile("cp.async.cg.shared.global [%0], [%1], 16;\n" :: "r"(sa), "l"(gsrc));
}

__device__ __forceinline__ void stage_chunk(const float* gsrc, float* sdst, int tid)
{
    // 8192 floats = 2048 float4s; 128 threads * 16 each, coalesced
#pragma unroll
    for (int i = 0; i < 16; ++i) {
        int idx = tid + i * SCAN_THREADS;   // 0..2047
        cp_async16(sdst + idx * 4, gsrc + idx * 4);
    }
}

__device__ __forceinline__ void grid_barrier()
{
    __syncthreads();
    if (threadIdx.x == 0) {
        __threadfence();
        unsigned long long old = atomicAdd(&g_bar, 1ULL);
        unsigned long long target = (old / NCTA + 1ULL) * (unsigned long long)NCTA;
        unsigned long long cur;
        do {
            asm volatile("ld.volatile.global.u64 %0, [%1];" : "=l"(cur) : "l"(&g_bar));
        } while (cur < target);
        __threadfence();
    }
    __syncthreads();
}

// ---------------------------------------------------------------------------
// Kernel 2: persistent recurrent scan.
// grid = 128 CTAs (single wave, guaranteed resident), 128 threads each.
// CTA b owns output columns [8b, 8b+8). Wh slice (1024x8 = 32KB) lives in smem
// for all 1024 steps. h_prev (transposed) staged through smem in 8 chunks of
// 128 k, cp.async double-buffered. Per thread: 4 rows x 1 col.
// out[t] holds xproj on entry and h_t on exit. Cross-step sync: grid barrier.
// ---------------------------------------------------------------------------
__global__ void __launch_bounds__(SCAN_THREADS) scan_kernel(
    const float* __restrict__ W,      // Wh = rows [512, 1536)
    float* __restrict__ out)
{
    extern __shared__ float smem[];
    float* whs = smem;                  // [1024][8] = 8192 floats (32KB)
    float* hbuf0 = smem + 8192;         // [128][64] chunk buffer A (32KB)
    float* hbuf1 = smem + 8192 + 8192;  // chunk buffer B (32KB)

    const int tid   = threadIdx.x;
    const int col0  = blockIdx.x * COLS_PER_CTA;
    const int c     = tid & 7;                // column within CTA tile
    const int rquad = (tid >> 3) << 2;        // base row (0,4,...,60)

    // Load resident Wh slice: whs[k*8 + cc] = Wh[k][col0+cc]
    for (int i = tid; i < H_DIM * COLS_PER_CTA; i += SCAN_THREADS) {
        int k  = i >> 3;
        int cc = i & 7;
        whs[i] = W[(size_t)(IN_DIM + k) * H_DIM + col0 + cc];
    }
    __syncthreads();

    for (int t = 0; t < T_STEPS; ++t) {
        const float* gh  = g_ht[t & 1];
        float*       ghn = g_ht[(t + 1) & 1];
        float*       outt = out + (size_t)t * BATCH * H_DIM;

        // prefetch xproj values for my 4 outputs
        float xp0 = outt[(rquad + 0) * H_DIM + col0 + c];
        float xp1 = outt[(rquad + 1) * H_DIM + col0 + c];
        float xp2 = outt[(rquad + 2) * H_DIM + col0 + c];
        float xp3 = outt[(rquad + 3) * H_DIM + col0 + c];

        float a0 = 0.f, a1 = 0.f, a2 = 0.f, a3 = 0.f;

        // stage chunk 0
        stage_chunk(gh, hbuf0, tid);
        asm volatile("cp.async.commit_group;\n" ::: "memory");

        for (int kc = 0; kc < NCHUNKS; ++kc) {
            float* buf = (kc & 1) ? hbuf1 : hbuf0;
            if (kc + 1 < NCHUNKS) {
                float* nbuf = ((kc + 1) & 1) ? hbuf1 : hbuf0;
                stage_chunk(gh + (size_t)(kc + 1) * KCHUNK * BATCH, nbuf, tid);
                asm volatile("cp.async.commit_group;\n" ::: "memory");
                asm volatile("cp.async.wait_group 1;\n" ::: "memory");
            } else {
                asm volatile("cp.async.wait_group 0;\n" ::: "memory");
            }
            __syncthreads();

            const float* whk = whs + kc * KCHUNK * 8;
#pragma unroll 8
            for (int k = 0; k < KCHUNK; ++k) {
                float4 hv = *(const float4*)(buf + k * BATCH + rquad);
                float  w  = whk[k * 8 + c];
                a0 = fmaf(hv.x, w, a0);
                a1 = fmaf(hv.y, w, a1);
                a2 = fmaf(hv.z, w, a2);
                a3 = fmaf(hv.w, w, a3);
            }
            __syncthreads();
        }

        float v0 = tanhf(a0 + xp0);
        float v1 = tanhf(a1 + xp1);
        float v2 = tanhf(a2 + xp2);
        float v3 = tanhf(a3 + xp3);

        // write hidden state to output history
        outt[(rquad + 0) * H_DIM + col0 + c] = v0;
        outt[(rquad + 1) * H_DIM + col0 + c] = v1;
        outt[(rquad + 2) * H_DIM + col0 + c] = v2;
        outt[(rquad + 3) * H_DIM + col0 + c] = v3;

        // write transposed copy for next step's staging (contiguous float4)
        *(float4*)&ghn[(col0 + c) * BATCH + rquad] = make_float4(v0, v1, v2, v3);

        grid_barrier();
    }
}

// ---------------------------------------------------------------------------
extern "C" void kernel_launch(void* const* d_in, const int* in_sizes, int n_in,
                              void* d_out, int out_size)
{
    (void)in_sizes; (void)n_in; (void)out_size;
    const float* x = (const float*)d_in[0];
    const float* h = (const float*)d_in[1];
    const float* W = (const float*)d_in[2];
    const float* b = (const float*)d_in[3];
    float* out = (float*)d_out;

    // 0) transpose initial hidden state into g_ht[0]
    transpose_h_kernel<<<64, 1024>>>(h);

    // 1) xproj = x @ Wx + b  -> out
    dim3 grid_x(H_DIM / 64, (T_STEPS * BATCH) / 64);
    xproj_kernel<<<grid_x, 256>>>(x, W, b, out);

    // 2) persistent recurrent scan
    cudaFuncSetAttribute(scan_kernel, cudaFuncAttributeMaxDynamicSharedMemorySize,
                         96 * 1024);
    scan_kernel<<<NCTA, SCAN_THREADS, 96 * 1024>>>(W, out);
}

// round 2
// speedup vs baseline: 1.5452x; 1.5452x over previous
#include <cuda_runtime.h>
#include <math.h>
#include <stdint.h>

#define T_STEPS 1024
#define BATCH   64
#define IN_DIM  512
#define H_DIM   1024

#define NCTA         128
#define SCAN_THREADS 128
#define COLS_PER_CTA 8          // 128 CTAs * 8 cols = 1024 = H_DIM
#define KCHUNK       256        // k-chunk staged in smem per double-buffer slot
#define NCHUNKS      (H_DIM / KCHUNK)   // 4
#define WH_PITCH     1028       // padded row pitch for [c][k] weight layout

// Transposed hidden state, double-buffered: g_ht[p][col*BATCH + row]
__device__ float g_ht[2][H_DIM * BATCH];
// Monotonic grid barrier counter (u64: never wraps across graph replays)
__device__ unsigned long long g_bar = 0ULL;

// ---------------------------------------------------------------------------
// Kernel 0: transpose initial h (B,H) into g_ht[0] (H,B)
// ---------------------------------------------------------------------------
__global__ void transpose_h_kernel(const float* __restrict__ h)
{
    int idx = blockIdx.x * blockDim.x + threadIdx.x;   // 0 .. 65535
    int r = idx >> 10;          // batch row 0..63
    int c = idx & 1023;         // hidden col 0..1023
    g_ht[0][c * BATCH + r] = h[idx];
}

// ---------------------------------------------------------------------------
// Kernel 1: xproj = x @ Wx + b  written into out (doubles as xproj buffer)
// M = T*B = 65536, K = IN_DIM = 512, N = H_DIM = 1024
// Tiles: BM=64, BN=64, BK=16; 256 threads; 4x4 per-thread microtile.
// ---------------------------------------------------------------------------
__global__ void __launch_bounds__(256) xproj_kernel(
    const float* __restrict__ x,
    const float* __restrict__ W,     // full (IN+H, H); Wx = rows [0,512)
    const float* __restrict__ bias,
    float* __restrict__ out)
{
    __shared__ float As[16][64];     // [k][m]
    __shared__ float Bs[16][64];     // [k][n]

    const int tid  = threadIdx.x;
    const int row0 = blockIdx.y * 64;
    const int col0 = blockIdx.x * 64;

    const int ty = tid >> 4;               // 0..15 (row group)
    const int tx = tid & 15;               // 0..15 (col group)

    const int lmA = tid >> 2;              // 0..63
    const int lkA = (tid & 3) << 2;        // 0,4,8,12
    const int lkB = tid >> 4;              // 0..15
    const int lnB = (tid & 15) << 2;       // 0..60

    float acc[4][4];
#pragma unroll
    for (int i = 0; i < 4; ++i)
#pragma unroll
        for (int j = 0; j < 4; ++j) acc[i][j] = 0.0f;

    const float* xg = x + (size_t)(row0 + lmA) * IN_DIM + lkA;

    for (int k0 = 0; k0 < IN_DIM; k0 += 16) {
        float4 av = *(const float4*)(xg + k0);
        As[lkA + 0][lmA] = av.x;
        As[lkA + 1][lmA] = av.y;
        As[lkA + 2][lmA] = av.z;
        As[lkA + 3][lmA] = av.w;

        float4 bv = *(const float4*)(W + (size_t)(k0 + lkB) * H_DIM + col0 + lnB);
        *(float4*)&Bs[lkB][lnB] = bv;

        __syncthreads();
#pragma unroll
        for (int k = 0; k < 16; ++k) {
            float4 a = *(const float4*)&As[k][ty << 2];
            float4 b = *(const float4*)&Bs[k][tx << 2];
            acc[0][0] = fmaf(a.x, b.x, acc[0][0]);
            acc[0][1] = fmaf(a.x, b.y, acc[0][1]);
            acc[0][2] = fmaf(a.x, b.z, acc[0][2]);
            acc[0][3] = fmaf(a.x, b.w, acc[0][3]);
            acc[1][0] = fmaf(a.y, b.x, acc[1][0]);
            acc[1][1] = fmaf(a.y, b.y, acc[1][1]);
            acc[1][2] = fmaf(a.y, b.z, acc[1][2]);
            acc[1][3] = fmaf(a.y, b.w, acc[1][3]);
            acc[2][0] = fmaf(a.z, b.x, acc[2][0]);
            acc[2][1] = fmaf(a.z, b.y, acc[2][1]);
            acc[2][2] = fmaf(a.z, b.z, acc[2][2]);
            acc[2][3] = fmaf(a.z, b.w, acc[2][3]);
            acc[3][0] = fmaf(a.w, b.x, acc[3][0]);
            acc[3][1] = fmaf(a.w, b.y, acc[3][1]);
            acc[3][2] = fmaf(a.w, b.z, acc[3][2]);
            acc[3][3] = fmaf(a.w, b.w, acc[3][3]);
        }
        __syncthreads();
    }

    float4 bb = *(const float4*)(bias + col0 + (tx << 2));
#pragma unroll
    for (int i = 0; i < 4; ++i) {
        float4 o;
        o.x = acc[i][0] + bb.x;
        o.y = acc[i][1] + bb.y;
        o.z = acc[i][2] + bb.z;
        o.w = acc[i][3] + bb.w;
        *(float4*)(out + (size_t)(row0 + (ty << 2) + i) * H_DIM + col0 + (tx << 2)) = o;
    }
}

// ---------------------------------------------------------------------------
// Scan kernel helpers
// ---------------------------------------------------------------------------
__device__ __forceinline__ void cp_async16(float* sdst, const float* gsrc)
{
    unsigned sa = (unsigned)__cvta_generic_to_shared(sdst);
    asm volatile("cp.async.cg.shared.global [%0], [%1], 16;\n" :: "r"(sa), "l"(gsrc));
}

__device__ __forceinline__ void stage_chunk(const float* gsrc, float* sdst, int tid)
{
    // KCHUNK*BATCH = 16384 floats = 4096 float4s; 128 threads * 32 each
#pragma unroll
    for (int i = 0; i < 32; ++i) {
        int idx = tid + i * SCAN_THREADS;   // 0..4095
        cp_async16(sdst + idx * 4, gsrc + idx * 4);
    }
}

__device__ __forceinline__ void grid_barrier()
{
    __syncthreads();
    if (threadIdx.x == 0) {
        __threadfence();
        unsigned long long old = atomicAdd(&g_bar, 1ULL);
        unsigned long long target = (old / NCTA + 1ULL) * (unsigned long long)NCTA;
        unsigned long long cur;
        do {
            asm volatile("ld.volatile.global.u64 %0, [%1];" : "=l"(cur) : "l"(&g_bar));
        } while (cur < target);
        __threadfence();
    }
    __syncthreads();
}

// ---------------------------------------------------------------------------
// Kernel 2: persistent recurrent scan.
// grid = 128 CTAs (single wave), 128 threads each.
// CTA b owns output columns [8b, 8b+8). Wh slice stored [c][k] (padded) in
// smem for the whole kernel -> float4 weight loads. h_prev staged through
// smem in 4 chunks of 256 k, cp.async double-buffered (one BAR per chunk).
// Per thread: 4 rows x 1 col. xp for step t+1 prefetched before the grid
// barrier so its DRAM latency hides under the barrier wait.
// ---------------------------------------------------------------------------
__global__ void __launch_bounds__(SCAN_THREADS) scan_kernel(
    const float* __restrict__ W,      // Wh = rows [512, 1536)
    float* __restrict__ out)
{
    extern __shared__ float smem[];
    float* whs   = smem;                        // [8][1028] padded = 8224 floats
    float* hbuf0 = smem + 8 * WH_PITCH;         // [256][64] chunk buffer A (64KB)
    float* hbuf1 = hbuf0 + KCHUNK * BATCH;      // chunk buffer B (64KB)

    const int tid   = threadIdx.x;
    const int col0  = blockIdx.x * COLS_PER_CTA;
    const int c     = tid & 7;                // column within CTA tile
    const int rquad = (tid >> 3) << 2;        // base row (0,4,...,60)

    // Load resident Wh slice, transposed: whs[cc*WH_PITCH + k] = Wh[k][col0+cc]
    for (int i = tid; i < H_DIM * COLS_PER_CTA; i += SCAN_THREADS) {
        int cc = i >> 10;        // 0..7
        int k  = i & 1023;       // 0..1023
        whs[cc * WH_PITCH + k] = W[(size_t)(IN_DIM + k) * H_DIM + col0 + cc];
    }
    __syncthreads();

    const float* wc = whs + c * WH_PITCH;
    const size_t out_off0 = (size_t)(rquad + 0) * H_DIM + col0 + c;
    const size_t out_off1 = (size_t)(rquad + 1) * H_DIM + col0 + c;
    const size_t out_off2 = (size_t)(rquad + 2) * H_DIM + col0 + c;
    const size_t out_off3 = (size_t)(rquad + 3) * H_DIM + col0 + c;

    // prefetch xp for step 0
    float xp0 = out[out_off0];
    float xp1 = out[out_off1];
    float xp2 = out[out_off2];
    float xp3 = out[out_off3];

    for (int t = 0; t < T_STEPS; ++t) {
        const float* gh  = g_ht[t & 1];
        float*       ghn = g_ht[(t + 1) & 1];
        float*       outt = out + (size_t)t * BATCH * H_DIM;

        float a0 = 0.f, a1 = 0.f, a2 = 0.f, a3 = 0.f;

        // stage chunk 0
        stage_chunk(gh, hbuf0, tid);
        asm volatile("cp.async.commit_group;\n" ::: "memory");

#pragma unroll
        for (int kc = 0; kc < NCHUNKS; ++kc) {
            asm volatile("cp.async.wait_group 0;\n" ::: "memory");
            __syncthreads();
            if (kc + 1 < NCHUNKS) {
                float* nbuf = ((kc + 1) & 1) ? hbuf1 : hbuf0;
                stage_chunk(gh + (size_t)(kc + 1) * KCHUNK * BATCH, nbuf, tid);
                asm volatile("cp.async.commit_group;\n" ::: "memory");
            }

            const float* buf = (kc & 1) ? hbuf1 : hbuf0;
            const float* wck = wc + kc * KCHUNK;
#pragma unroll 2
            for (int kk = 0; kk < KCHUNK; kk += 4) {
                float4 w4 = *(const float4*)(wck + kk);
                float4 h0 = *(const float4*)(buf + (kk + 0) * BATCH + rquad);
                float4 h1 = *(const float4*)(buf + (kk + 1) * BATCH + rquad);
                float4 h2 = *(const float4*)(buf + (kk + 2) * BATCH + rquad);
                float4 h3 = *(const float4*)(buf + (kk + 3) * BATCH + rquad);
                a0 = fmaf(h0.x, w4.x, a0);
                a1 = fmaf(h0.y, w4.x, a1);
                a2 = fmaf(h0.z, w4.x, a2);
                a3 = fmaf(h0.w, w4.x, a3);
                a0 = fmaf(h1.x, w4.y, a0);
                a1 = fmaf(h1.y, w4.y, a1);
                a2 = fmaf(h1.z, w4.y, a2);
                a3 = fmaf(h1.w, w4.y, a3);
                a0 = fmaf(h2.x, w4.z, a0);
                a1 = fmaf(h2.y, w4.z, a1);
                a2 = fmaf(h2.z, w4.z, a2);
                a3 = fmaf(h2.w, w4.z, a3);
                a0 = fmaf(h3.x, w4.w, a0);
                a1 = fmaf(h3.y, w4.w, a1);
                a2 = fmaf(h3.z, w4.w, a2);
                a3 = fmaf(h3.w, w4.w, a3);
            }
        }

        float v0 = tanhf(a0 + xp0);
        float v1 = tanhf(a1 + xp1);
        float v2 = tanhf(a2 + xp2);
        float v3 = tanhf(a3 + xp3);

        // write hidden state to output history
        outt[out_off0] = v0;
        outt[out_off1] = v1;
        outt[out_off2] = v2;
        outt[out_off3] = v3;

        // write transposed copy for next step's staging (contiguous float4)
        *(float4*)&ghn[(col0 + c) * BATCH + rquad] = make_float4(v0, v1, v2, v3);

        // prefetch next step's xp (own-column data: no cross-CTA dependency);
        // DRAM latency hides under the grid barrier wait
        if (t + 1 < T_STEPS) {
            const float* outn = outt + BATCH * H_DIM;
            xp0 = outn[out_off0];
            xp1 = outn[out_off1];
            xp2 = outn[out_off2];
            xp3 = outn[out_off3];
        }

        grid_barrier();
    }
}

// ---------------------------------------------------------------------------
extern "C" void kernel_launch(void* const* d_in, const int* in_sizes, int n_in,
                              void* d_out, int out_size)
{
    (void)in_sizes; (void)n_in; (void)out_size;
    const float* x = (const float*)d_in[0];
    const float* h = (const float*)d_in[1];
    const float* W = (const float*)d_in[2];
    const float* b = (const float*)d_in[3];
    float* out = (float*)d_out;

    // 0) transpose initial hidden state into g_ht[0]
    transpose_h_kernel<<<64, 1024>>>(h);

    // 1) xproj = x @ Wx + b  -> out
    dim3 grid_x(H_DIM / 64, (T_STEPS * BATCH) / 64);
    xproj_kernel<<<grid_x, 256>>>(x, W, b, out);

    // 2) persistent recurrent scan
    static int smem_set = 0;
    if (!smem_set) {
        cudaFuncSetAttribute(scan_kernel, cudaFuncAttributeMaxDynamicSharedMemorySize,
                             (8 * WH_PITCH + 2 * KCHUNK * BATCH) * sizeof(float));
        smem_set = 1;
    }
    scan_kernel<<<NCTA, SCAN_THREADS,
                  (8 * WH_PITCH + 2 * KCHUNK * BATCH) * sizeof(float)>>>(W, out);
}

// round 3
// speedup vs baseline: 1.8102x; 1.1715x over previous
#include <cuda_runtime.h>
#include <math.h>
#include <stdint.h>

typedef unsigned long long ull;

#define T_STEPS 1024
#define BATCH   64
#define IN_DIM  512
#define H_DIM   1024

#define NCTA         128
#define SCAN_THREADS 256
#define COLS_PER_CTA 8          // 128 CTAs * 8 cols = 1024 = H_DIM
#define KCHUNK       256        // k-chunk staged in smem per double-buffer slot
#define NCHUNKS      (H_DIM / KCHUNK)   // 4
#define WPK_PITCH    1030       // ull pitch per column row (bank-conflict-free)

// Transposed hidden state, double-buffered: g_ht[p][col*BATCH + row]
__device__ float g_ht[2][H_DIM * BATCH];
// Monotonic grid barrier counter (u64: never wraps across graph replays)
__device__ ull g_bar = 0ULL;

// ---------------------------------------------------------------------------
// packed f32x2 helpers (Blackwell sm_103a)
// ---------------------------------------------------------------------------
__device__ __forceinline__ ull pack2(float a, float b)
{
    ull r; asm("mov.b64 %0, {%1, %2};" : "=l"(r) : "f"(a), "f"(b)); return r;
}
__device__ __forceinline__ void unpack2(ull v, float& a, float& b)
{
    asm("mov.b64 {%0, %1}, %2;" : "=f"(a), "=f"(b) : "l"(v));
}
__device__ __forceinline__ void fma2(ull& acc, ull a, ull b)
{
    asm("fma.rn.f32x2 %0, %1, %2, %0;" : "+l"(acc) : "l"(a), "l"(b));
}
__device__ __forceinline__ ull add2(ull a, ull b)
{
    ull r; asm("add.rn.f32x2 %0, %1, %2;" : "=l"(r) : "l"(a), "l"(b)); return r;
}

// ---------------------------------------------------------------------------
// Kernel 0: transpose initial h (B,H) into g_ht[0] (H,B)
// ---------------------------------------------------------------------------
__global__ void transpose_h_kernel(const float* __restrict__ h)
{
    int idx = blockIdx.x * blockDim.x + threadIdx.x;   // 0 .. 65535
    int r = idx >> 10;          // batch row 0..63
    int c = idx & 1023;         // hidden col 0..1023
    g_ht[0][c * BATCH + r] = h[idx];
}

// ---------------------------------------------------------------------------
// Kernel 1: xproj = x @ Wx + b  (out doubles as xproj buffer)
// M=65536, K=512, N=1024. BM=64, BN=64, BK=16; 256 threads; 4x4 microtile,
// accumulators held as packed f32x2 pairs -> 8 FFMA2 per k per thread.
// ---------------------------------------------------------------------------
__global__ void __launch_bounds__(256) xproj_kernel(
    const float* __restrict__ x,
    const float* __restrict__ W,     // full (IN+H, H); Wx = rows [0,512)
    const float* __restrict__ bias,
    float* __restrict__ out)
{
    __shared__ float As[16][64];     // [k][m]
    __shared__ float Bs[16][64];     // [k][n]

    const int tid  = threadIdx.x;
    const int row0 = blockIdx.y * 64;
    const int col0 = blockIdx.x * 64;

    const int ty = tid >> 4;               // 0..15 (row group)
    const int tx = tid & 15;               // 0..15 (col group)

    const int lmA = tid >> 2;              // 0..63
    const int lkA = (tid & 3) << 2;        // 0,4,8,12
    const int lkB = tid >> 4;              // 0..15
    const int lnB = (tid & 15) << 2;       // 0..60

    ull acc01[4], acc23[4];
#pragma unroll
    for (int i = 0; i < 4; ++i) { acc01[i] = 0ULL; acc23[i] = 0ULL; }

    const float* xg = x + (size_t)(row0 + lmA) * IN_DIM + lkA;

    for (int k0 = 0; k0 < IN_DIM; k0 += 16) {
        float4 av = *(const float4*)(xg + k0);
        As[lkA + 0][lmA] = av.x;
        As[lkA + 1][lmA] = av.y;
        As[lkA + 2][lmA] = av.z;
        As[lkA + 3][lmA] = av.w;

        float4 bv = *(const float4*)(W + (size_t)(k0 + lkB) * H_DIM + col0 + lnB);
        *(float4*)&Bs[lkB][lnB] = bv;

        __syncthreads();
#pragma unroll
        for (int k = 0; k < 16; ++k) {
            float4 a = *(const float4*)&As[k][ty << 2];
            ulonglong2 b = *(const ulonglong2*)&Bs[k][tx << 2];  // (b0,b1),(b2,b3)
            ull ax = pack2(a.x, a.x);
            ull ay = pack2(a.y, a.y);
            ull az = pack2(a.z, a.z);
            ull aw = pack2(a.w, a.w);
            fma2(acc01[0], ax, b.x); fma2(acc23[0], ax, b.y);
            fma2(acc01[1], ay, b.x); fma2(acc23[1], ay, b.y);
            fma2(acc01[2], az, b.x); fma2(acc23[2], az, b.y);
            fma2(acc01[3], aw, b.x); fma2(acc23[3], aw, b.y);
        }
        __syncthreads();
    }

    float4 bb = *(const float4*)(bias + col0 + (tx << 2));
#pragma unroll
    for (int i = 0; i < 4; ++i) {
        float s0, s1, s2, s3;
        unpack2(acc01[i], s0, s1);
        unpack2(acc23[i], s2, s3);
        float4 o;
        o.x = s0 + bb.x;
        o.y = s1 + bb.y;
        o.z = s2 + bb.z;
        o.w = s3 + bb.w;
        *(float4*)(out + (size_t)(row0 + (ty << 2) + i) * H_DIM + col0 + (tx << 2)) = o;
    }
}

// ---------------------------------------------------------------------------
// Scan kernel helpers
// ---------------------------------------------------------------------------
__device__ __forceinline__ void cp_async16(float* sdst, const float* gsrc)
{
    unsigned sa = (unsigned)__cvta_generic_to_shared(sdst);
    asm volatile("cp.async.cg.shared.global [%0], [%1], 16;\n" :: "r"(sa), "l"(gsrc));
}

__device__ __forceinline__ void stage_chunk(const float* gsrc, float* sdst, int tid)
{
    // KCHUNK*BATCH = 16384 floats = 4096 float4s; 256 threads * 16 each
#pragma unroll
    for (int i = 0; i < 16; ++i) {
        int idx = tid + i * SCAN_THREADS;   // 0..4095
        cp_async16(sdst + idx * 4, gsrc + idx * 4);
    }
}

__device__ __forceinline__ void grid_barrier()
{
    __syncthreads();
    if (threadIdx.x == 0) {
        __threadfence();
        ull old = atomicAdd(&g_bar, 1ULL);
        ull target = (old / NCTA + 1ULL) * (ull)NCTA;
        ull cur;
        do {
            asm volatile("ld.volatile.global.u64 %0, [%1];" : "=l"(cur) : "l"(&g_bar));
        } while (cur < target);
        __threadfence();
    }
    __syncthreads();
}

// ---------------------------------------------------------------------------
// Kernel 2: persistent recurrent scan.
// 128 CTAs (single wave) x 256 threads (8 warps, 2 per SMSP).
// CTA owns 8 output columns. Wh slice pre-packed (w,w) as f32x2 in smem,
// layout [c][k] with pitch 1030 ull -> conflict-free LDS.128 (2 weights/load).
// h_prev staged through smem in 4 chunks of 256 k, cp.async double-buffered.
// Thread groups split each chunk's K in half (both groups active every chunk);
// cross-group reduction via smem + add.rn.f32x2.
// Inner math uses packed fma.rn.f32x2 (FFMA2) -> 2x fp32 FMA throughput.
// ---------------------------------------------------------------------------
__global__ void __launch_bounds__(SCAN_THREADS) scan_kernel(
    const float* __restrict__ W,      // Wh = rows [512, 1536)
    float* __restrict__ out)
{
    extern __shared__ float smem[];
    ull*   wpk   = (ull*)smem;                          // 8 x 1030 ull = 65920 B
    float* hbuf0 = smem + 2 * 8 * WPK_PITCH;            // [256][64] floats (64 KB)
    float* hbuf1 = hbuf0 + KCHUNK * BATCH;              // (64 KB)
    ulonglong2* red = (ulonglong2*)hbuf0;               // reused after last chunk

    const int tid   = threadIdx.x;
    const int lid   = tid & 127;              // lane within group
    const int grp   = tid >> 7;               // 0 or 1 (k-split group)
    const int col0  = blockIdx.x * COLS_PER_CTA;
    const int c     = lid & 7;                 // column within CTA tile
    const int rquad = (lid >> 3) << 2;         // base row (0,4,...,60)

    // Pre-pack resident Wh slice: wpk[cc][k] = (w, w)
    for (int i = tid; i < H_DIM * COLS_PER_CTA; i += SCAN_THREADS) {
        int cc = i >> 10;        // 0..7
        int k  = i & 1023;       // 0..1023
        float w = W[(size_t)(IN_DIM + k) * H_DIM + col0 + cc];
        wpk[cc * WPK_PITCH + k] = pack2(w, w);
    }
    __syncthreads();

    const ull* wc = wpk + c * WPK_PITCH + grp * 128;   // group k-offset baked in

    const size_t out_off0 = (size_t)(rquad + 0) * H_DIM + col0 + c;
    const size_t out_off1 = (size_t)(rquad + 1) * H_DIM + col0 + c;
    const size_t out_off2 = (size_t)(rquad + 2) * H_DIM + col0 + c;
    const size_t out_off3 = (size_t)(rquad + 3) * H_DIM + col0 + c;

    // prefetch xp for step 0 (lower group computes the epilogue)
    float xp0 = 0.f, xp1 = 0.f, xp2 = 0.f, xp3 = 0.f;
    if (grp == 0) {
        xp0 = out[out_off0];
        xp1 = out[out_off1];
        xp2 = out[out_off2];
        xp3 = out[out_off3];
    }

    for (int t = 0; t < T_STEPS; ++t) {
        const float* gh  = g_ht[t & 1];
        float*       ghn = g_ht[(t + 1) & 1];
        float*       outt = out + (size_t)t * BATCH * H_DIM;

        ull a01 = 0ULL, a23 = 0ULL;

        // stage chunk 0
        stage_chunk(gh, hbuf0, tid);
        asm volatile("cp.async.commit_group;\n" ::: "memory");

#pragma unroll
        for (int kc = 0; kc < NCHUNKS; ++kc) {
            asm volatile("cp.async.wait_group 0;\n" ::: "memory");
            __syncthreads();
            if (kc + 1 < NCHUNKS) {
                float* nbuf = ((kc + 1) & 1) ? hbuf1 : hbuf0;
                stage_chunk(gh + (size_t)(kc + 1) * KCHUNK * BATCH, nbuf, tid);
                asm volatile("cp.async.commit_group;\n" ::: "memory");
            }

            const float* buf = (kc & 1) ? hbuf1 : hbuf0;
            const float* hb  = buf + grp * 128 * BATCH + rquad;  // my K half
            const ull*   wck = wc + kc * KCHUNK;                 // my K half weights
#pragma unroll 8
            for (int kk = 0; kk < 128; kk += 4) {
                ulonglong2 w01 = *(const ulonglong2*)(wck + kk);      // (w_k,w_k),(w_k+1,w_k+1)
                ulonglong2 w23 = *(const ulonglong2*)(wck + kk + 2);
                ulonglong2 h0 = *(const ulonglong2*)(hb + (kk + 0) * BATCH);
                ulonglong2 h1 = *(const ulonglong2*)(hb + (kk + 1) * BATCH);
                ulonglong2 h2 = *(const ulonglong2*)(hb + (kk + 2) * BATCH);
                ulonglong2 h3 = *(const ulonglong2*)(hb + (kk + 3) * BATCH);
                fma2(a01, h0.x, w01.x); fma2(a23, h0.y, w01.x);
                fma2(a01, h1.x, w01.y); fma2(a23, h1.y, w01.y);
                fma2(a01, h2.x, w23.x); fma2(a23, h2.y, w23.x);
                fma2(a01, h3.x, w23.y); fma2(a23, h3.y, w23.y);
            }
        }

        // cross-group reduction (red lives in hbuf0; last chunk read hbuf1)
        if (grp == 1) {
            red[lid] = make_ulonglong2(a01, a23);
        }
        __syncthreads();

        if (grp == 0) {
            ulonglong2 r = red[lid];
            a01 = add2(a01, r.x);
            a23 = add2(a23, r.y);

            float s0, s1, s2, s3;
            unpack2(a01, s0, s1);
            unpack2(a23, s2, s3);
            float v0 = tanhf(s0 + xp0);
            float v1 = tanhf(s1 + xp1);
            float v2 = tanhf(s2 + xp2);
            float v3 = tanhf(s3 + xp3);

            // write hidden state to output history
            outt[out_off0] = v0;
            outt[out_off1] = v1;
            outt[out_off2] = v2;
            outt[out_off3] = v3;

            // transposed copy for next step's staging (contiguous float4)
            *(float4*)&ghn[(col0 + c) * BATCH + rquad] = make_float4(v0, v1, v2, v3);

            // prefetch next step's xp; DRAM latency hides under the barrier
            if (t + 1 < T_STEPS) {
                const float* outn = outt + BATCH * H_DIM;
                xp0 = outn[out_off0];
                xp1 = outn[out_off1];
                xp2 = outn[out_off2];
                xp3 = outn[out_off3];
            }
        }

        grid_barrier();
    }
}

// ---------------------------------------------------------------------------
extern "C" void kernel_launch(void* const* d_in, const int* in_sizes, int n_in,
                              void* d_out, int out_size)
{
    (void)in_sizes; (void)n_in; (void)out_size;
    const float* x = (const float*)d_in[0];
    const float* h = (const float*)d_in[1];
    const float* W = (const float*)d_in[2];
    const float* b = (const float*)d_in[3];
    float* out = (float*)d_out;

    // 0) transpose initial hidden state into g_ht[0]
    transpose_h_kernel<<<64, 1024>>>(h);

    // 1) xproj = x @ Wx + b  -> out
    dim3 grid_x(H_DIM / 64, (T_STEPS * BATCH) / 64);
    xproj_kernel<<<grid_x, 256>>>(x, W, b, out);

    // 2) persistent recurrent scan
    const size_t smem_bytes = (2 * 8 * WPK_PITCH + 2 * KCHUNK * BATCH) * sizeof(float);
    static int smem_set = 0;
    if (!smem_set) {
        cudaFuncSetAttribute(scan_kernel, cudaFuncAttributeMaxDynamicSharedMemorySize,
                             (int)smem_bytes);
        smem_set = 1;
    }
    scan_kernel<<<NCTA, SCAN_THREADS, smem_bytes>>>(W, out);
}